// round 6
// baseline (speedup 1.0000x reference)
#include <cuda_runtime.h>
#include <cuda_bf16.h>
#include <stdint.h>

#define NN 96
#define DD 64
#define CC 30

// Scratch (__device__ globals; no allocation allowed)
__device__ float    g_mat[NN * NN];
__device__ unsigned g_smask[NN * 3];
__device__ unsigned g_dmask[NN * 3];
__device__ unsigned g_count;   // grid barrier (monotonic; +96 per launch)

// ---------------------------------------------------------------------------
// Mega-kernel: 96 blocks x 1024 threads, everything in one launch.
//   Phase 1 (blocks 0..8): cosine mat, one output/thread (9*1024 = 96*96).
//           (blocks 9..11): label masks via warp ballots.
//   Phase Z (all blocks):  zero prefixes (k <= j) of anchor bid's 96 slabs
//                          -> 172 MB of stores hiding prep latency.
//   Grid barrier (monotonic counter, +96/launch -> graph-replay-safe).
//   Phase 2 (all blocks):  redundant bit-identical epsilon, cmask ballots
//                          into SMEM, then the data half (k > j).
// ---------------------------------------------------------------------------
__global__ __launch_bounds__(1024) void mega(const float* __restrict__ logits,
                                             const float* __restrict__ labels,
                                             float4* __restrict__ out) {
    __shared__ float    sx[NN * 65];
    __shared__ float    rn[NN];
    __shared__ float    s_rnum[NN], s_rq[NN];
    __shared__ float    s_eps;
    __shared__ float    srow[NN];
    __shared__ unsigned scm[NN * 3];     // this anchor's c-mask (96 x 96 bits)
    __shared__ unsigned sm[3], dm[3];

    const int tid  = threadIdx.x;
    const int bid  = blockIdx.x;
    const int warp = tid >> 5, lane = tid & 31;

    // ======================= Phase 1: prep (12 blocks) =======================
    if (bid < 9) {
        #pragma unroll
        for (int it = 0; it < 6; it++) {
            int t = it * 1024 + tid;                  // 6144 = 96*64
            sx[(t >> 6) * 65 + (t & 63)] = logits[t];
        }
        __syncthreads();
        if (tid < NN) {                               // norms (bit-identical order)
            float s = 0.f;
            #pragma unroll
            for (int d = 0; d < DD; d++) { float v = sx[tid * 65 + d]; s += v * v; }
            rn[tid] = rsqrtf(s);
        }
        __syncthreads();
        const int outp = bid * 1024 + tid;            // 0..9215
        const int r = outp / NN;                      // warp-uniform (96 = 3 warps)
        const int c = outp - r * NN;
        float acc = 0.f;
        #pragma unroll
        for (int d = 0; d < DD; d++) acc += sx[r * 65 + d] * sx[c * 65 + d];
        g_mat[outp] = -acc * rn[r] * rn[c];
    } else if (bid < 12) {
        // reuse sx for labels (NN*CC = 2880 <= NN*65)
        #pragma unroll
        for (int it = 0; it < 3; it++) {
            int t = it * 1024 + tid;                  // 2880 = 96*30
            if (t < NN * CC) sx[t] = labels[t];
        }
        __syncthreads();
        const int i = (bid - 9) * 32 + warp;          // row 0..95
        #pragma unroll
        for (int wd = 0; wd < 3; wd++) {
            int j = wd * 32 + lane;
            float acc = 0.f;
            #pragma unroll
            for (int cc = 0; cc < CC; cc++) acc += sx[i * CC + cc] * sx[j * CC + cc];
            bool same_raw = acc > 0.f;
            unsigned sb = __ballot_sync(0xffffffffu, same_raw && (j != i));
            unsigned db = __ballot_sync(0xffffffffu, !same_raw);
            if (lane == 0) {
                g_smask[i * 3 + wd] = sb;
                g_dmask[i * 3 + wd] = db;
            }
        }
    }
    // Release phase-1 writes BEFORE the big zero stream so the fence is cheap
    // (each thread has at most a few outstanding global stores here).
    __threadfence();

    // ======================= Phase Z: zero half (k <= j) =====================
    {
        const float4 z4 = make_float4(0.f, 0.f, 0.f, 0.f);
        float4* sb = out + (size_t)bid * NN * 2304;   // anchor's 96 slabs
        for (int j = 0; j < NN; j++) {
            float4* o = sb + (size_t)j * 2304;
            const int len = (j + 1) * 24;             // (j+1) k-rows of 24 float4
            for (int pos = tid; pos < len; pos += 1024)
                __stcs(o + pos, z4);
        }
    }

    // ======================= Grid barrier =======================
    __syncthreads();
    if (tid == 0) {
        unsigned prev   = atomicAdd(&g_count, 1u);
        unsigned target = (prev / 96u + 1u) * 96u;    // end of THIS launch's wave
        while (*(volatile unsigned*)&g_count < target) { }
        __threadfence();                              // acquire phase-1 writes
    }
    __syncthreads();

    // ======================= Phase 2: eps + cmask + data half ================
    const int ianc = bid;

    // epsilon: identical math/order in every block -> deterministic
    for (int i = warp; i < NN; i += 32) {
        float S = 0.f, ds = 0.f, ms = 0.f, md = 0.f;
        #pragma unroll
        for (int jj = 0; jj < 3; jj++) {
            float mv = g_mat[i * NN + jj * 32 + lane];
            if ((g_smask[i * 3 + jj] >> lane) & 1u) { S += 1.f; ms += mv; }
            if ((g_dmask[i * 3 + jj] >> lane) & 1u) { ds += 1.f; md += mv; }
        }
        #pragma unroll
        for (int o = 16; o; o >>= 1) {
            S  += __shfl_xor_sync(0xffffffffu, S,  o);
            ds += __shfl_xor_sync(0xffffffffu, ds, o);
            ms += __shfl_xor_sync(0xffffffffu, ms, o);
            md += __shfl_xor_sync(0xffffffffu, md, o);
        }
        if (lane == 0) {
            s_rnum[i] = (S - 1.f) * (S * md - ms * ds);
            s_rq[i]   = 0.5f * S * (S - 1.f) * ds;
        }
    }
    if (tid < NN) srow[tid] = g_mat[ianc * NN + tid];
    if (tid >= NN && tid < NN + 3) {
        sm[tid - NN] = g_smask[ianc * 3 + (tid - NN)];
        dm[tid - NN] = g_dmask[ianc * 3 + (tid - NN)];
    }
    __syncthreads();
    if (tid == 0) {   // serial reduce: identical order every block
        float num = 0.f, q = 0.f;
        for (int i = 0; i < NN; i++) { num += s_rnum[i]; q += s_rq[i]; }
        float mean_delta = num / fmaxf(2.f * q, 1.f);
        s_eps = fmaxf(mean_delta * 0.5f, 0.f);   // relu(mean_delta / K_DELTA)
    }
    __syncthreads();
    const float eps = s_eps;

    // cmask for this anchor -> SMEM (same ballot math as the passing kernel)
    for (int p = warp; p < NN; p += 32) {
        unsigned sp = (sm[p >> 5] >> (p & 31)) & 1u;
        float matp = srow[p];
        #pragma unroll
        for (int wd = 0; wd < 3; wd++) {
            float m = srow[wd * 32 + lane] - matp;
            bool cc = sp && (((dm[wd] >> lane) & 1u) != 0u) && (m > 0.f) && (m <= eps);
            unsigned b = __ballot_sync(0xffffffffu, cc);
            if (lane == 0) scm[p * 3 + wd] = b;
        }
    }
    __syncthreads();

    // data half: for each slab j, rows k = j+1 .. 95
    {
        const unsigned ONEF = 0x3f800000u;
        float4* sb = out + (size_t)ianc * NN * 2304;
        for (int j = 0; j < NN - 1; j++) {
            const unsigned wj0 = scm[j * 3 + 0];
            const unsigned wj1 = scm[j * 3 + 1];
            const unsigned wj2 = scm[j * 3 + 2];
            const int len = (NN - 1 - j) * 24;
            float4* o = sb + (size_t)j * 2304 + (j + 1) * 24;
            for (int pos = tid; pos < len; pos += 1024) {
                int q  = pos / 24;                   // row index offset
                int r  = pos - q * 24;               // float4 within row
                int k  = j + 1 + q;
                int wd = r >> 3;
                unsigned wj = (wd == 0) ? wj0 : ((wd == 1) ? wj1 : wj2);
                unsigned w  = wj & scm[k * 3 + wd];
                unsigned b  = w >> ((r & 7) * 4);
                float4 v;
                v.x = __uint_as_float(ONEF & (0u - (b & 1u)));
                v.y = __uint_as_float(ONEF & (0u - ((b >> 1) & 1u)));
                v.z = __uint_as_float(ONEF & (0u - ((b >> 2) & 1u)));
                v.w = __uint_as_float(ONEF & (0u - ((b >> 3) & 1u)));
                __stcs(o + pos, v);
            }
        }
    }
}

// ---------------------------------------------------------------------------
extern "C" void kernel_launch(void* const* d_in, const int* in_sizes, int n_in,
                              void* d_out, int out_size) {
    const float* logits = (const float*)d_in[0];   // [96,64]
    const float* labels = (const float*)d_in[1];   // [96,30]

    mega<<<NN, 1024>>>(logits, labels, (float4*)d_out);
}

// round 7
// speedup vs baseline: 1.3237x; 1.3237x over previous
#include <cuda_runtime.h>
#include <cuda_bf16.h>
#include <stdint.h>

#define NN 96
#define DD 64
#define CC 30
#define PREP_BLOCKS 48   // 36 mat + 12 label blocks; also = cmask workers (2 anchors each)

// Scratch (__device__ globals; no allocation allowed)
__device__ float    g_mat[NN * NN];
__device__ unsigned g_smask[NN * 3];
__device__ unsigned g_dmask[NN * 3];
__device__ unsigned g_cmask[NN * NN * 4];   // 96-bit mask per (i,p), stride 4 words
__device__ unsigned g_count;                 // barrier among 48 prep blocks (monotonic)

// ---------------------------------------------------------------------------
// K1: grid = 48 + 9216 blocks x 256 threads.
//   blocks 0..35   : cosine mat, one output per thread (36*256 = 96*96)
//   blocks 36..47  : label masks via warp ballots (8 rows per block)
//   ...all 48 then barrier (co-resident: wave 1), compute eps redundantly
//      (bit-identical order), and build cmask for 2 anchors each.
//   blocks 48..9263: zero the k<=j prefix of slab (bid-48) -> 172 MB of
//      streaming stores that HIDE the prep latency.
// ---------------------------------------------------------------------------
__global__ __launch_bounds__(256) void k1_prep_zero(const float* __restrict__ logits,
                                                    const float* __restrict__ labels,
                                                    float4* __restrict__ out) {
    const int tid = threadIdx.x;
    const int bid = blockIdx.x;

    if (bid >= PREP_BLOCKS) {
        // ---------------- zero half: slab r2, rows k = 0..j ----------------
        const int r2 = bid - PREP_BLOCKS;            // i*96 + j
        const int j  = r2 % NN;
        float4* o = out + (size_t)r2 * 2304;
        const int len = (j + 1) * 24;
        const float4 z4 = make_float4(0.f, 0.f, 0.f, 0.f);
        for (int pos = tid; pos < len; pos += 256)
            __stcs(o + pos, z4);
        return;
    }

    // ======================= prep blocks (0..47) =======================
    __shared__ float    sx[NN * 65];
    __shared__ float    rn[NN];
    __shared__ float    s_rnum[NN], s_rq[NN];
    __shared__ float    s_eps;
    __shared__ float    srow[NN];
    __shared__ unsigned sm[3], dm[3];

    const int warp = tid >> 5, lane = tid & 31;

    if (bid < 36) {
        // ---- mat: one output per thread ----
        #pragma unroll
        for (int it = 0; it < 24; it++) {             // 6144 = 24*256
            int t = it * 256 + tid;
            sx[(t >> 6) * 65 + (t & 63)] = logits[t];
        }
        __syncthreads();
        if (tid < NN) {                               // norms (bit-identical order)
            float s = 0.f;
            #pragma unroll
            for (int d = 0; d < DD; d++) { float v = sx[tid * 65 + d]; s += v * v; }
            rn[tid] = rsqrtf(s);
        }
        __syncthreads();
        const int outp = bid * 256 + tid;             // 0..9215
        const int r = outp / NN;
        const int c = outp - r * NN;
        float acc = 0.f;
        #pragma unroll
        for (int d = 0; d < DD; d++) acc += sx[r * 65 + d] * sx[c * 65 + d];
        g_mat[outp] = -acc * rn[r] * rn[c];
    } else {
        // ---- labels: one warp per row, 8 rows per block ----
        #pragma unroll
        for (int it = 0; it < 12; it++) {             // 2880 = 96*30
            int t = it * 256 + tid;
            if (t < NN * CC) sx[t] = labels[t];
        }
        __syncthreads();
        const int i = (bid - 36) * 8 + warp;          // row 0..95
        #pragma unroll
        for (int wd = 0; wd < 3; wd++) {
            int j = wd * 32 + lane;
            float acc = 0.f;
            #pragma unroll
            for (int cc = 0; cc < CC; cc++) acc += sx[i * CC + cc] * sx[j * CC + cc];
            bool same_raw = acc > 0.f;
            unsigned sb = __ballot_sync(0xffffffffu, same_raw && (j != i));
            unsigned db = __ballot_sync(0xffffffffu, !same_raw);
            if (lane == 0) {
                g_smask[i * 3 + wd] = sb;
                g_dmask[i * 3 + wd] = db;
            }
        }
    }

    // ---- barrier among the 48 prep blocks (all in wave 1 -> co-resident) ----
    __threadfence();                                  // publish mat / masks
    __syncthreads();
    if (tid == 0) {
        unsigned prev   = atomicAdd(&g_count, 1u);
        unsigned target = (prev / PREP_BLOCKS + 1u) * PREP_BLOCKS;
        while (*(volatile unsigned*)&g_count < target) { }
        __threadfence();                              // acquire
    }
    __syncthreads();

    // ---- epsilon: identical math/order in every block -> deterministic ----
    for (int i = warp; i < NN; i += 8) {
        float S = 0.f, ds = 0.f, ms = 0.f, md = 0.f;
        #pragma unroll
        for (int jj = 0; jj < 3; jj++) {
            float mv = g_mat[i * NN + jj * 32 + lane];
            if ((g_smask[i * 3 + jj] >> lane) & 1u) { S += 1.f; ms += mv; }
            if ((g_dmask[i * 3 + jj] >> lane) & 1u) { ds += 1.f; md += mv; }
        }
        #pragma unroll
        for (int o = 16; o; o >>= 1) {
            S  += __shfl_xor_sync(0xffffffffu, S,  o);
            ds += __shfl_xor_sync(0xffffffffu, ds, o);
            ms += __shfl_xor_sync(0xffffffffu, ms, o);
            md += __shfl_xor_sync(0xffffffffu, md, o);
        }
        if (lane == 0) {
            s_rnum[i] = (S - 1.f) * (S * md - ms * ds);
            s_rq[i]   = 0.5f * S * (S - 1.f) * ds;
        }
    }
    __syncthreads();
    if (tid == 0) {   // serial reduce: identical order every block
        float num = 0.f, q = 0.f;
        for (int i = 0; i < NN; i++) { num += s_rnum[i]; q += s_rq[i]; }
        float mean_delta = num / fmaxf(2.f * q, 1.f);
        s_eps = fmaxf(mean_delta * 0.5f, 0.f);   // relu(mean_delta / K_DELTA)
    }
    __syncthreads();
    const float eps = s_eps;

    // ---- cmask for 2 anchors per block ----
    #pragma unroll
    for (int a0 = 0; a0 < 2; a0++) {
        const int ianc = bid * 2 + a0;
        if (tid < NN) srow[tid] = g_mat[ianc * NN + tid];
        if (tid >= NN && tid < NN + 3) {
            sm[tid - NN] = g_smask[ianc * 3 + (tid - NN)];
            dm[tid - NN] = g_dmask[ianc * 3 + (tid - NN)];
        }
        __syncthreads();
        for (int p = warp; p < NN; p += 8) {
            unsigned sp = (sm[p >> 5] >> (p & 31)) & 1u;
            float matp = srow[p];
            #pragma unroll
            for (int wd = 0; wd < 3; wd++) {
                float m = srow[wd * 32 + lane] - matp;
                bool cc = sp && (((dm[wd] >> lane) & 1u) != 0u) && (m > 0.f) && (m <= eps);
                unsigned b = __ballot_sync(0xffffffffu, cc);
                if (lane == 0) g_cmask[(ianc * NN + p) * 4 + wd] = b;
            }
        }
        __syncthreads();
    }
}

// ---------------------------------------------------------------------------
// K2: data half. One block per (i,j), writes rows k = j+1..95 only
// (168 MB). Same staging as the proven 49us writer, suffix-only.
// ---------------------------------------------------------------------------
__global__ __launch_bounds__(256) void k2_write(float4* __restrict__ out) {
    __shared__ unsigned sw[NN * 3];
    const int r2 = blockIdx.x;           // i*96 + j
    const int j  = r2 % NN;
    if (j == NN - 1) return;             // empty suffix
    const int ibase = r2 - j;            // i*96
    const int tid = threadIdx.x;

    for (int t = tid; t < NN * 3; t += 256) {
        int k  = t / 3;
        int wd = t - k * 3;
        unsigned v = 0u;
        if (k > j)
            v = g_cmask[(r2 << 2) + wd] & g_cmask[((ibase + k) << 2) + wd];
        sw[t] = v;
    }
    __syncthreads();

    float4* o = out + (size_t)r2 * 2304 + (j + 1) * 24;
    const int len = (NN - 1 - j) * 24;
    const unsigned ONEF = 0x3f800000u;
    for (int pos = tid; pos < len; pos += 256) {
        int q  = pos / 24;
        int r  = pos - q * 24;
        int k  = j + 1 + q;
        unsigned w = sw[k * 3 + (r >> 3)];
        unsigned b = w >> ((r & 7) * 4);
        float4 v;
        v.x = __uint_as_float(ONEF & (0u - (b & 1u)));
        v.y = __uint_as_float(ONEF & (0u - ((b >> 1) & 1u)));
        v.z = __uint_as_float(ONEF & (0u - ((b >> 2) & 1u)));
        v.w = __uint_as_float(ONEF & (0u - ((b >> 3) & 1u)));
        __stcs(o + pos, v);
    }
}

// ---------------------------------------------------------------------------
extern "C" void kernel_launch(void* const* d_in, const int* in_sizes, int n_in,
                              void* d_out, int out_size) {
    const float* logits = (const float*)d_in[0];   // [96,64]
    const float* labels = (const float*)d_in[1];   // [96,30]

    k1_prep_zero<<<PREP_BLOCKS + NN * NN, 256>>>(logits, labels, (float4*)d_out);
    k2_write<<<NN * NN, 256>>>((float4*)d_out);
}

// round 8
// speedup vs baseline: 1.3244x; 1.0006x over previous
#include <cuda_runtime.h>
#include <cuda_bf16.h>
#include <stdint.h>

#define NN 96
#define DD 64
#define CC 30
#define PREP_BLOCKS 48   // 36 mat + 12 label blocks; then 2 anchors/block for cmask

// Scratch (__device__ globals; no allocation allowed)
__device__ float    g_mat[NN * NN];
__device__ unsigned g_smask[NN * 3];
__device__ unsigned g_dmask[NN * 3];
__device__ unsigned g_cmask[NN * NN * 4];   // 96-bit mask per (i,p), stride 4 words
__device__ unsigned g_count;                 // barrier among prep blocks (monotonic)

// ---------------------------------------------------------------------------
// K1: grid = 48 prep + 4608 zero blocks x 256 threads (prep blocks first ->
// scheduled in wave 1, hidden under the 172 MB zero stream).
//   Zero blocks: anchor i, slab pair (j1 = p, j2 = 95-p). Zero prefixes
//   (k <= j) of both slabs: (j1+1)+(j2+1) = 97 rows = 2328 float4 -> UNIFORM.
// ---------------------------------------------------------------------------
__global__ __launch_bounds__(256) void k1_prep_zero(const float* __restrict__ logits,
                                                    const float* __restrict__ labels,
                                                    float4* __restrict__ out) {
    const int tid = threadIdx.x;
    const int bid = blockIdx.x;

    if (bid >= PREP_BLOCKS) {
        // ---------------- zero half, paired & uniform ----------------
        const int zid = bid - PREP_BLOCKS;            // 0..4607
        const int i   = zid / 48;
        const int p   = zid - i * 48;                 // 0..47
        const int j1  = p;
        const int j2  = NN - 1 - p;
        const int len1 = (j1 + 1) * 24;               // prefix of slab j1
        const int len2 = (j2 + 1) * 24;               // prefix of slab j2
        float4* o1 = out + ((size_t)i * NN + j1) * 2304;
        float4* o2 = out + ((size_t)i * NN + j2) * 2304;
        const float4 z4 = make_float4(0.f, 0.f, 0.f, 0.f);
        const int total = len1 + len2;                // 2328 always
        for (int pos = tid; pos < total; pos += 256) {
            int p2 = pos - len1;
            if (p2 < 0) __stcs(o1 + pos, z4);
            else        __stcs(o2 + p2,  z4);
        }
        return;
    }

    // ======================= prep blocks (0..47) =======================
    __shared__ float    sx[NN * 65];
    __shared__ float    rn[NN];
    __shared__ float    s_rnum[NN], s_rq[NN];
    __shared__ float    s_eps;
    __shared__ float    srow[NN];
    __shared__ unsigned sm[3], dm[3];

    const int warp = tid >> 5, lane = tid & 31;

    if (bid < 36) {
        // ---- mat: one output per thread ----
        #pragma unroll
        for (int it = 0; it < 24; it++) {             // 6144 = 24*256
            int t = it * 256 + tid;
            sx[(t >> 6) * 65 + (t & 63)] = logits[t];
        }
        __syncthreads();
        if (tid < NN) {                               // norms (bit-identical order)
            float s = 0.f;
            #pragma unroll
            for (int d = 0; d < DD; d++) { float v = sx[tid * 65 + d]; s += v * v; }
            rn[tid] = rsqrtf(s);
        }
        __syncthreads();
        const int outp = bid * 256 + tid;             // 0..9215
        const int r = outp / NN;
        const int c = outp - r * NN;
        float acc = 0.f;
        #pragma unroll
        for (int d = 0; d < DD; d++) acc += sx[r * 65 + d] * sx[c * 65 + d];
        g_mat[outp] = -acc * rn[r] * rn[c];
    } else {
        // ---- labels: one warp per row, 8 rows per block ----
        #pragma unroll
        for (int it = 0; it < 12; it++) {             // 2880 = 96*30
            int t = it * 256 + tid;
            if (t < NN * CC) sx[t] = labels[t];
        }
        __syncthreads();
        const int i = (bid - 36) * 8 + warp;          // row 0..95
        #pragma unroll
        for (int wd = 0; wd < 3; wd++) {
            int j = wd * 32 + lane;
            float acc = 0.f;
            #pragma unroll
            for (int cc = 0; cc < CC; cc++) acc += sx[i * CC + cc] * sx[j * CC + cc];
            bool same_raw = acc > 0.f;
            unsigned sb = __ballot_sync(0xffffffffu, same_raw && (j != i));
            unsigned db = __ballot_sync(0xffffffffu, !same_raw);
            if (lane == 0) {
                g_smask[i * 3 + wd] = sb;
                g_dmask[i * 3 + wd] = db;
            }
        }
    }

    // ---- barrier among the 48 prep blocks (all in wave 1 -> co-resident) ----
    __threadfence();                                  // publish mat / masks
    __syncthreads();
    if (tid == 0) {
        unsigned prev   = atomicAdd(&g_count, 1u);
        unsigned target = (prev / PREP_BLOCKS + 1u) * PREP_BLOCKS;
        while (*(volatile unsigned*)&g_count < target) { }
        __threadfence();                              // acquire
    }
    __syncthreads();

    // ---- epsilon: identical math/order in every block -> deterministic ----
    for (int i = warp; i < NN; i += 8) {
        float S = 0.f, ds = 0.f, ms = 0.f, md = 0.f;
        #pragma unroll
        for (int jj = 0; jj < 3; jj++) {
            float mv = g_mat[i * NN + jj * 32 + lane];
            if ((g_smask[i * 3 + jj] >> lane) & 1u) { S += 1.f; ms += mv; }
            if ((g_dmask[i * 3 + jj] >> lane) & 1u) { ds += 1.f; md += mv; }
        }
        #pragma unroll
        for (int o = 16; o; o >>= 1) {
            S  += __shfl_xor_sync(0xffffffffu, S,  o);
            ds += __shfl_xor_sync(0xffffffffu, ds, o);
            ms += __shfl_xor_sync(0xffffffffu, ms, o);
            md += __shfl_xor_sync(0xffffffffu, md, o);
        }
        if (lane == 0) {
            s_rnum[i] = (S - 1.f) * (S * md - ms * ds);
            s_rq[i]   = 0.5f * S * (S - 1.f) * ds;
        }
    }
    __syncthreads();
    if (tid == 0) {   // serial reduce: identical order every block
        float num = 0.f, q = 0.f;
        for (int i = 0; i < NN; i++) { num += s_rnum[i]; q += s_rq[i]; }
        float mean_delta = num / fmaxf(2.f * q, 1.f);
        s_eps = fmaxf(mean_delta * 0.5f, 0.f);   // relu(mean_delta / K_DELTA)
    }
    __syncthreads();
    const float eps = s_eps;

    // ---- cmask for 2 anchors per block ----
    #pragma unroll
    for (int a0 = 0; a0 < 2; a0++) {
        const int ianc = bid * 2 + a0;
        if (tid < NN) srow[tid] = g_mat[ianc * NN + tid];
        if (tid >= NN && tid < NN + 3) {
            sm[tid - NN] = g_smask[ianc * 3 + (tid - NN)];
            dm[tid - NN] = g_dmask[ianc * 3 + (tid - NN)];
        }
        __syncthreads();
        for (int p = warp; p < NN; p += 8) {
            unsigned sp = (sm[p >> 5] >> (p & 31)) & 1u;
            float matp = srow[p];
            #pragma unroll
            for (int wd = 0; wd < 3; wd++) {
                float m = srow[wd * 32 + lane] - matp;
                bool cc = sp && (((dm[wd] >> lane) & 1u) != 0u) && (m > 0.f) && (m <= eps);
                unsigned b = __ballot_sync(0xffffffffu, cc);
                if (lane == 0) g_cmask[(ianc * NN + p) * 4 + wd] = b;
            }
        }
        __syncthreads();
    }
}

// ---------------------------------------------------------------------------
// K2: data half, paired & uniform. Block = (i, pair p): slabs j1 = p,
// j2 = 95-p. Suffix rows (k > j): (95-j1)+(95-j2) = 95 rows = 2280 float4
// per block -> UNIFORM. Both slabs' AND-masks staged in smem.
// ---------------------------------------------------------------------------
__global__ __launch_bounds__(256) void k2_write(float4* __restrict__ out) {
    __shared__ unsigned sw1[NN * 3], sw2[NN * 3];
    const int bid = blockIdx.x;          // 0..4607
    const int i   = bid / 48;
    const int p   = bid - i * 48;
    const int j1  = p;
    const int j2  = NN - 1 - p;
    const int ibase = i * NN;
    const int tid = threadIdx.x;

    for (int t = tid; t < NN * 3; t += 256) {
        int k  = t / 3;
        int wd = t - k * 3;
        unsigned ck = g_cmask[((ibase + k) << 2) + wd];
        sw1[t] = (k > j1) ? (g_cmask[((ibase + j1) << 2) + wd] & ck) : 0u;
        sw2[t] = (k > j2) ? (g_cmask[((ibase + j2) << 2) + wd] & ck) : 0u;
    }
    __syncthreads();

    const int len1 = (NN - 1 - j1) * 24;             // suffix of slab j1
    float4* o1 = out + ((size_t)ibase + j1) * 2304 + (j1 + 1) * 24;
    float4* o2 = out + ((size_t)ibase + j2) * 2304 + (j2 + 1) * 24;
    const unsigned ONEF = 0x3f800000u;

    for (int pos = tid; pos < 95 * 24; pos += 256) {
        int p2 = pos - len1;
        bool first = (p2 < 0);
        int pp = first ? pos : p2;
        int q  = pp / 24;
        int r  = pp - q * 24;
        int k  = (first ? j1 : j2) + 1 + q;
        unsigned w = (first ? sw1 : sw2)[k * 3 + (r >> 3)];
        unsigned b = w >> ((r & 7) * 4);
        float4 v;
        v.x = __uint_as_float(ONEF & (0u - (b & 1u)));
        v.y = __uint_as_float(ONEF & (0u - ((b >> 1) & 1u)));
        v.z = __uint_as_float(ONEF & (0u - ((b >> 2) & 1u)));
        v.w = __uint_as_float(ONEF & (0u - ((b >> 3) & 1u)));
        __stcs((first ? o1 : o2) + pp, v);
    }
}

// ---------------------------------------------------------------------------
extern "C" void kernel_launch(void* const* d_in, const int* in_sizes, int n_in,
                              void* d_out, int out_size) {
    const float* logits = (const float*)d_in[0];   // [96,64]
    const float* labels = (const float*)d_in[1];   // [96,30]

    k1_prep_zero<<<PREP_BLOCKS + NN * 48, 256>>>(logits, labels, (float4*)d_out);
    k2_write<<<NN * 48, 256>>>((float4*)d_out);
}